// round 5
// baseline (speedup 1.0000x reference)
#include <cuda_runtime.h>
#include <math.h>
#include <stdint.h>

// ---------------- problem constants ----------------
#define BATCH   4
#define LSEQ    1024
#define DM      512
#define DI      1024      // d_inner
#define DS      16        // d_state
#define DTR     32        // dt_rank
#define NROWS   (BATCH*LSEQ)   // 4096
#define LN_EPS  1e-5f

// ---------------- scratch (device globals; no allocs allowed) ----------------
__device__ float g_xinT[BATCH * DI * LSEQ];   // in_proj x-half, [b][d][t]
__device__ float g_zT  [BATCH * DI * LSEQ];   // silu(z), [b][d][t]
__device__ float g_xsT [BATCH * DI * LSEQ];   // conv+silu, [b][d][t] (scan)
__device__ float g_xs  [NROWS * DI];          // conv+silu, [row][d]  (proj)
__device__ float g_BT  [BATCH * DS * LSEQ];   // B, [b][n][t]
__device__ float g_CT  [BATCH * DS * LSEQ];   // C, [b][n][t]
__device__ float g_dT  [BATCH * DI * LSEQ];   // delta, [b][d][t]
__device__ float g_y   [NROWS * DI];          // scan out (gated), [row][d]
__device__ float g_res [NROWS * DM];          // out_proj + residual (LN input)

// ---------------- tf32 helpers ----------------
__device__ __forceinline__ uint32_t f2tf32(float x) {
    uint32_t r;
    asm("cvt.rna.tf32.f32 %0, %1;" : "=r"(r) : "f"(x));
    return r;
}

__device__ __forceinline__ void mma_tf32(
    float& d0, float& d1, float& d2, float& d3,
    uint32_t a0, uint32_t a1, uint32_t a2, uint32_t a3,
    uint32_t b0, uint32_t b1)
{
    asm volatile(
        "mma.sync.aligned.m16n8k8.row.col.f32.tf32.tf32.f32 "
        "{%0,%1,%2,%3}, {%4,%5,%6,%7}, {%8,%9}, {%0,%1,%2,%3};\n"
        : "+f"(d0), "+f"(d1), "+f"(d2), "+f"(d3)
        : "r"(a0), "r"(a1), "r"(a2), "r"(a3), "r"(b0), "r"(b1));
}

__device__ __forceinline__ float silu_f(float x) {
    return __fdividef(x, 1.f + __expf(-x));
}

// ---------------- tensor-core GEMM: C[M,N] = A[M,K] @ B[K,N] ----------------
// modes:
//  1: C[row][col] = acc + aux[row][col]              (residual)
//  3: transposed split: col<DI -> xinT[b][col][t], else silu -> zT[b][col-DI][t]
#define BM 128
#define BN 64
#define BK 32

__global__ __launch_bounds__(256) void mma_gemm(
    const float* __restrict__ A, const float* __restrict__ B,
    float* __restrict__ C, const float* __restrict__ aux,
    int K, int lda, int ldb, int ldc, int mode)
{
    __shared__ uint32_t As[BM][36];
    __shared__ uint32_t Bs[BK][68];

    const int tid = threadIdx.x;
    const int bm = blockIdx.y * BM;
    const int bn = blockIdx.x * BN;
    const int w  = tid >> 5;
    const int lane = tid & 31;
    const int g  = lane >> 2;
    const int tg = lane & 3;
    const int wm = (w & 3) * 32;
    const int wn = (w >> 2) * 32;

    const int ra = tid >> 3;
    const int ca = (tid & 7) * 4;
    const int rb = tid >> 4;
    const int cb = (tid & 15) * 4;

    float acc[2][4][4];
#pragma unroll
    for (int i = 0; i < 2; i++)
#pragma unroll
        for (int j = 0; j < 4; j++)
#pragma unroll
            for (int r = 0; r < 4; r++) acc[i][j][r] = 0.f;

    const int nk = K / BK;

    float4 pa[4], pb[2];
#pragma unroll
    for (int p = 0; p < 4; p++)
        pa[p] = *(const float4*)(A + (size_t)(bm + ra + p * 32) * lda + ca);
#pragma unroll
    for (int p = 0; p < 2; p++)
        pb[p] = *(const float4*)(B + (size_t)(rb + p * 16) * ldb + bn + cb);

    for (int kb = 0; kb < nk; kb++) {
#pragma unroll
        for (int p = 0; p < 4; p++) {
            uint4 v;
            v.x = f2tf32(pa[p].x); v.y = f2tf32(pa[p].y);
            v.z = f2tf32(pa[p].z); v.w = f2tf32(pa[p].w);
            *(uint4*)&As[ra + p * 32][ca] = v;
        }
#pragma unroll
        for (int p = 0; p < 2; p++) {
            uint4 v;
            v.x = f2tf32(pb[p].x); v.y = f2tf32(pb[p].y);
            v.z = f2tf32(pb[p].z); v.w = f2tf32(pb[p].w);
            *(uint4*)&Bs[rb + p * 16][cb] = v;
        }
        __syncthreads();

        if (kb + 1 < nk) {
            int k0 = (kb + 1) * BK;
#pragma unroll
            for (int p = 0; p < 4; p++)
                pa[p] = *(const float4*)(A + (size_t)(bm + ra + p * 32) * lda + k0 + ca);
#pragma unroll
            for (int p = 0; p < 2; p++)
                pb[p] = *(const float4*)(B + (size_t)(k0 + rb + p * 16) * ldb + bn + cb);
        }

#pragma unroll
        for (int ks = 0; ks < 4; ks++) {
            const int k8 = ks * 8;
            uint32_t af[2][4];
#pragma unroll
            for (int mt = 0; mt < 2; mt++) {
                int r0 = wm + mt * 16 + g;
                af[mt][0] = As[r0][k8 + tg];
                af[mt][1] = As[r0 + 8][k8 + tg];
                af[mt][2] = As[r0][k8 + tg + 4];
                af[mt][3] = As[r0 + 8][k8 + tg + 4];
            }
#pragma unroll
            for (int nt = 0; nt < 4; nt++) {
                int c0 = wn + nt * 8 + g;
                uint32_t b0 = Bs[k8 + tg][c0];
                uint32_t b1 = Bs[k8 + tg + 4][c0];
#pragma unroll
                for (int mt = 0; mt < 2; mt++)
                    mma_tf32(acc[mt][nt][0], acc[mt][nt][1],
                             acc[mt][nt][2], acc[mt][nt][3],
                             af[mt][0], af[mt][1], af[mt][2], af[mt][3],
                             b0, b1);
            }
        }
        __syncthreads();
    }

#pragma unroll
    for (int mt = 0; mt < 2; mt++) {
#pragma unroll
        for (int nt = 0; nt < 4; nt++) {
            int grow = bm + wm + mt * 16 + g;
            int gcol = bn + wn + nt * 8 + 2 * tg;
            float v0 = acc[mt][nt][0], v1 = acc[mt][nt][1];
            float v2 = acc[mt][nt][2], v3 = acc[mt][nt][3];
            if (mode == 1) {
                float2 r0 = *(const float2*)(aux + (size_t)grow * ldc + gcol);
                float2 r1 = *(const float2*)(aux + (size_t)(grow + 8) * ldc + gcol);
                v0 += r0.x; v1 += r0.y; v2 += r1.x; v3 += r1.y;
                float2 o0 = {v0, v1}, o1 = {v2, v3};
                *(float2*)(C + (size_t)grow * ldc + gcol) = o0;
                *(float2*)(C + (size_t)(grow + 8) * ldc + gcol) = o1;
            } else { // mode 3: split-transpose (xin | silu(z))
                int b = grow >> 10;
                int t = grow & (LSEQ - 1);
                float* dst;
                int c;
                if (gcol < DI) { dst = g_xinT; c = gcol; }
                else {
                    dst = g_zT; c = gcol - DI;
                    v0 = silu_f(v0); v1 = silu_f(v1);
                    v2 = silu_f(v2); v3 = silu_f(v3);
                }
                float* base = dst + ((size_t)b * DI) * LSEQ;
                base[(size_t)c * LSEQ + t]           = v0;
                base[(size_t)(c + 1) * LSEQ + t]     = v1;
                base[(size_t)c * LSEQ + t + 8]       = v2;
                base[(size_t)(c + 1) * LSEQ + t + 8] = v3;
            }
        }
    }
}

// ---------------- fused x_proj + dt_proj kernel ----------------
// Phase 1: dbc[128,64] = xs_tile[128,1024] @ Wx[1024,64]
//          dt (cols 0..31) -> smem; B (32..47), C (48..63) -> g_BT/g_CT transposed.
// Phase 2: delta[128,1024] = softplus(dt @ Wdt + bdt), transposed -> g_dT.
__global__ __launch_bounds__(256) void proj_k(
    const float* __restrict__ Wx, const float* __restrict__ Wdt,
    const float* __restrict__ bdt)
{
    __shared__ uint32_t As[BM][36];
    __shared__ uint32_t Bs[BK][68];
    __shared__ float    dts[BM][33];

    const int tid = threadIdx.x;
    const int bm = blockIdx.x * BM;
    const int w  = tid >> 5;
    const int lane = tid & 31;
    const int g  = lane >> 2;
    const int tg = lane & 3;
    const int wm = (w & 3) * 32;
    const int wn = (w >> 2) * 32;

    const int ra = tid >> 3;
    const int ca = (tid & 7) * 4;
    const int rb = tid >> 4;
    const int cb = (tid & 15) * 4;

    float acc[2][4][4];
#pragma unroll
    for (int i = 0; i < 2; i++)
#pragma unroll
        for (int j = 0; j < 4; j++)
#pragma unroll
            for (int r = 0; r < 4; r++) acc[i][j][r] = 0.f;

    // ---- phase 1: xs @ Wx (K = 1024) ----
    const int nk = DI / BK;
    float4 pa[4], pb[2];
#pragma unroll
    for (int p = 0; p < 4; p++)
        pa[p] = *(const float4*)(g_xs + (size_t)(bm + ra + p * 32) * DI + ca);
#pragma unroll
    for (int p = 0; p < 2; p++)
        pb[p] = *(const float4*)(Wx + (size_t)(rb + p * 16) * 64 + cb);

    for (int kb = 0; kb < nk; kb++) {
#pragma unroll
        for (int p = 0; p < 4; p++) {
            uint4 v;
            v.x = f2tf32(pa[p].x); v.y = f2tf32(pa[p].y);
            v.z = f2tf32(pa[p].z); v.w = f2tf32(pa[p].w);
            *(uint4*)&As[ra + p * 32][ca] = v;
        }
#pragma unroll
        for (int p = 0; p < 2; p++) {
            uint4 v;
            v.x = f2tf32(pb[p].x); v.y = f2tf32(pb[p].y);
            v.z = f2tf32(pb[p].z); v.w = f2tf32(pb[p].w);
            *(uint4*)&Bs[rb + p * 16][cb] = v;
        }
        __syncthreads();

        if (kb + 1 < nk) {
            int k0 = (kb + 1) * BK;
#pragma unroll
            for (int p = 0; p < 4; p++)
                pa[p] = *(const float4*)(g_xs + (size_t)(bm + ra + p * 32) * DI + k0 + ca);
#pragma unroll
            for (int p = 0; p < 2; p++)
                pb[p] = *(const float4*)(Wx + (size_t)(k0 + rb + p * 16) * 64 + cb);
        }

#pragma unroll
        for (int ks = 0; ks < 4; ks++) {
            const int k8 = ks * 8;
            uint32_t af[2][4];
#pragma unroll
            for (int mt = 0; mt < 2; mt++) {
                int r0 = wm + mt * 16 + g;
                af[mt][0] = As[r0][k8 + tg];
                af[mt][1] = As[r0 + 8][k8 + tg];
                af[mt][2] = As[r0][k8 + tg + 4];
                af[mt][3] = As[r0 + 8][k8 + tg + 4];
            }
#pragma unroll
            for (int nt = 0; nt < 4; nt++) {
                int c0 = wn + nt * 8 + g;
                uint32_t b0 = Bs[k8 + tg][c0];
                uint32_t b1 = Bs[k8 + tg + 4][c0];
#pragma unroll
                for (int mt = 0; mt < 2; mt++)
                    mma_tf32(acc[mt][nt][0], acc[mt][nt][1],
                             acc[mt][nt][2], acc[mt][nt][3],
                             af[mt][0], af[mt][1], af[mt][2], af[mt][3],
                             b0, b1);
            }
        }
        __syncthreads();
    }

    // phase-1 epilogue: dt -> smem, B/C -> transposed gmem
#pragma unroll
    for (int mt = 0; mt < 2; mt++) {
#pragma unroll
        for (int nt = 0; nt < 4; nt++) {
            int lrow = wm + mt * 16 + g;
            int grow = bm + lrow;
            int gcol = wn + nt * 8 + 2 * tg;
            float v0 = acc[mt][nt][0], v1 = acc[mt][nt][1];
            float v2 = acc[mt][nt][2], v3 = acc[mt][nt][3];
            int b = grow >> 10;
            int t = grow & (LSEQ - 1);
            if (gcol < 32) {
                dts[lrow][gcol] = v0;     dts[lrow][gcol + 1] = v1;
                dts[lrow + 8][gcol] = v2; dts[lrow + 8][gcol + 1] = v3;
            } else if (gcol < 48) {
                int n0 = gcol - 32;
                float* base = g_BT + ((size_t)b * DS) * LSEQ;
                base[(size_t)n0 * LSEQ + t]           = v0;
                base[(size_t)(n0 + 1) * LSEQ + t]     = v1;
                base[(size_t)n0 * LSEQ + t + 8]       = v2;
                base[(size_t)(n0 + 1) * LSEQ + t + 8] = v3;
            } else {
                int n0 = gcol - 48;
                float* base = g_CT + ((size_t)b * DS) * LSEQ;
                base[(size_t)n0 * LSEQ + t]           = v0;
                base[(size_t)(n0 + 1) * LSEQ + t]     = v1;
                base[(size_t)n0 * LSEQ + t + 8]       = v2;
                base[(size_t)(n0 + 1) * LSEQ + t + 8] = v3;
            }
        }
    }
    __syncthreads();

    // ---- phase 2: delta = softplus(dt @ Wdt + bdt), N chunks of 64 ----
    // preload A fragments (register-resident for all chunks)
    uint32_t afc[4][2][4];
#pragma unroll
    for (int ks = 0; ks < 4; ks++) {
        const int k8 = ks * 8;
#pragma unroll
        for (int mt = 0; mt < 2; mt++) {
            int r0 = wm + mt * 16 + g;
            afc[ks][mt][0] = f2tf32(dts[r0][k8 + tg]);
            afc[ks][mt][1] = f2tf32(dts[r0 + 8][k8 + tg]);
            afc[ks][mt][2] = f2tf32(dts[r0][k8 + tg + 4]);
            afc[ks][mt][3] = f2tf32(dts[r0 + 8][k8 + tg + 4]);
        }
    }

    float4 pw[2];
#pragma unroll
    for (int p = 0; p < 2; p++)
        pw[p] = *(const float4*)(Wdt + (size_t)(rb + p * 16) * DI + cb);

    for (int nc = 0; nc < 16; nc++) {
#pragma unroll
        for (int p = 0; p < 2; p++) {
            uint4 v;
            v.x = f2tf32(pw[p].x); v.y = f2tf32(pw[p].y);
            v.z = f2tf32(pw[p].z); v.w = f2tf32(pw[p].w);
            *(uint4*)&Bs[rb + p * 16][cb] = v;
        }
        __syncthreads();

        if (nc + 1 < 16) {
#pragma unroll
            for (int p = 0; p < 2; p++)
                pw[p] = *(const float4*)(Wdt + (size_t)(rb + p * 16) * DI
                                         + (nc + 1) * 64 + cb);
        }

        float acc2[2][4][4];
#pragma unroll
        for (int i = 0; i < 2; i++)
#pragma unroll
            for (int j = 0; j < 4; j++)
#pragma unroll
                for (int r = 0; r < 4; r++) acc2[i][j][r] = 0.f;

#pragma unroll
        for (int ks = 0; ks < 4; ks++) {
            const int k8 = ks * 8;
#pragma unroll
            for (int nt = 0; nt < 4; nt++) {
                int c0 = wn + nt * 8 + g;
                uint32_t b0 = Bs[k8 + tg][c0];
                uint32_t b1 = Bs[k8 + tg + 4][c0];
#pragma unroll
                for (int mt = 0; mt < 2; mt++)
                    mma_tf32(acc2[mt][nt][0], acc2[mt][nt][1],
                             acc2[mt][nt][2], acc2[mt][nt][3],
                             afc[ks][mt][0], afc[ks][mt][1],
                             afc[ks][mt][2], afc[ks][mt][3],
                             b0, b1);
            }
        }
        __syncthreads();

        // epilogue: bias + softplus, transposed store to g_dT
#pragma unroll
        for (int mt = 0; mt < 2; mt++) {
#pragma unroll
            for (int nt = 0; nt < 4; nt++) {
                int grow = bm + wm + mt * 16 + g;
                int col = nc * 64 + wn + nt * 8 + 2 * tg;
                int b = grow >> 10;
                int t = grow & (LSEQ - 1);
                float b0 = bdt[col], b1 = bdt[col + 1];
                float v0 = acc2[mt][nt][0] + b0, v1 = acc2[mt][nt][1] + b1;
                float v2 = acc2[mt][nt][2] + b0, v3 = acc2[mt][nt][3] + b1;
                v0 = (v0 > 20.f) ? v0 : __logf(1.f + __expf(v0));
                v1 = (v1 > 20.f) ? v1 : __logf(1.f + __expf(v1));
                v2 = (v2 > 20.f) ? v2 : __logf(1.f + __expf(v2));
                v3 = (v3 > 20.f) ? v3 : __logf(1.f + __expf(v3));
                float* base = g_dT + ((size_t)b * DI) * LSEQ;
                base[(size_t)col * LSEQ + t]           = v0;
                base[(size_t)(col + 1) * LSEQ + t]     = v1;
                base[(size_t)col * LSEQ + t + 8]       = v2;
                base[(size_t)(col + 1) * LSEQ + t + 8] = v3;
            }
        }
    }
}

// ---------------- depthwise causal conv (k=4) + bias + silu, channel-major --
__global__ __launch_bounds__(256) void conv2_k(
    const float* __restrict__ cw, const float* __restrict__ cb)
{
    __shared__ float tin[32][68];
    __shared__ float tout[32][65];
    const int b  = blockIdx.z;
    const int d0 = blockIdx.y * 32;
    const int t0 = blockIdx.x * 64;
    const int tid = threadIdx.x;

    for (int i = tid; i < 32 * 67; i += 256) {
        int dd = i / 67, j = i % 67;
        int t = t0 - 3 + j;
        float v = 0.f;
        if (t >= 0) v = g_xinT[((size_t)(b * DI + d0 + dd)) * LSEQ + t];
        tin[dd][j] = v;
    }
    __syncthreads();

    const int dd = tid >> 3;
    const int tq = tid & 7;
    const float* wp = cw + (d0 + dd) * 4;
    float w0 = wp[0], w1 = wp[1], w2 = wp[2], w3 = wp[3];
    float bias = cb[d0 + dd];

    float res[8];
#pragma unroll
    for (int half = 0; half < 2; half++) {
#pragma unroll
        for (int i = 0; i < 4; i++) {
            int j = half * 32 + tq * 4 + i;
            float acc = bias;
            acc = fmaf(w0, tin[dd][j],     acc);
            acc = fmaf(w1, tin[dd][j + 1], acc);
            acc = fmaf(w2, tin[dd][j + 2], acc);
            acc = fmaf(w3, tin[dd][j + 3], acc);
            acc = silu_f(acc);
            res[half * 4 + i] = acc;
            tout[dd][j] = acc;
        }
    }
    float* dstT = g_xsT + ((size_t)(b * DI + d0 + dd)) * LSEQ + t0;
    *(float4*)(dstT + tq * 4)      = make_float4(res[0], res[1], res[2], res[3]);
    *(float4*)(dstT + 32 + tq * 4) = make_float4(res[4], res[5], res[6], res[7]);
    __syncthreads();

    const int dw = tid & 31;
    const int tw = tid >> 5;
#pragma unroll
    for (int it = 0; it < 8; it++) {
        int tl = it * 8 + tw;
        g_xs[((size_t)(b * LSEQ + t0 + tl)) * DI + d0 + dw] = tout[dw][tl];
    }
}

// ---------------- selective scan, fully prefetched streams -----------------
// 16 lanes per channel (one state each), 2 channels per warp, 128-thr blocks.
__global__ __launch_bounds__(128) void scan_k(
    const float* __restrict__ A_log, const float* __restrict__ Dsk)
{
    int tid = blockIdx.x * 128 + threadIdx.x;
    int w = tid >> 5;
    int lane = tid & 31;
    int half = lane >> 4;
    int n = lane & 15;
    int b = w / (DI / 2);
    int dp = w % (DI / 2);
    int d = dp * 2 + half;

    const float a  = -expf(A_log[d * DS + n]);
    const float Dv = Dsk[d];

    const float* dT = g_dT  + ((size_t)(b * DI + d)) * LSEQ;
    const float* xT = g_xsT + ((size_t)(b * DI + d)) * LSEQ;
    const float* zT = g_zT  + ((size_t)(b * DI + d)) * LSEQ;
    const float* BT = g_BT  + ((size_t)(b * DS + n)) * LSEQ;
    const float* CT = g_CT  + ((size_t)(b * DS + n)) * LSEQ;
    float*       yp = g_y   + ((size_t)b * LSEQ) * DI + d;

    // prefetch registers: all five streams, one 8-step group ahead
    float4 nd0 = *(const float4*)(dT),     nd1 = *(const float4*)(dT + 4);
    float4 nx0 = *(const float4*)(xT),     nx1 = *(const float4*)(xT + 4);
    float4 nz0 = *(const float4*)(zT),     nz1 = *(const float4*)(zT + 4);
    float4 nB0 = *(const float4*)(BT),     nB1 = *(const float4*)(BT + 4);
    float4 nC0 = *(const float4*)(CT),     nC1 = *(const float4*)(CT + 4);

    float h = 0.f;
    for (int t8 = 0; t8 < LSEQ; t8 += 8) {
        float dv[8] = {nd0.x, nd0.y, nd0.z, nd0.w, nd1.x, nd1.y, nd1.z, nd1.w};
        float xv[8] = {nx0.x, nx0.y, nx0.z, nx0.w, nx1.x, nx1.y, nx1.z, nx1.w};
        float zv[8] = {nz0.x, nz0.y, nz0.z, nz0.w, nz1.x, nz1.y, nz1.z, nz1.w};
        float Bn[8] = {nB0.x, nB0.y, nB0.z, nB0.w, nB1.x, nB1.y, nB1.z, nB1.w};
        float Cn[8] = {nC0.x, nC0.y, nC0.z, nC0.w, nC1.x, nC1.y, nC1.z, nC1.w};

        if (t8 + 8 < LSEQ) {
            nd0 = *(const float4*)(dT + t8 + 8);  nd1 = *(const float4*)(dT + t8 + 12);
            nx0 = *(const float4*)(xT + t8 + 8);  nx1 = *(const float4*)(xT + t8 + 12);
            nz0 = *(const float4*)(zT + t8 + 8);  nz1 = *(const float4*)(zT + t8 + 12);
            nB0 = *(const float4*)(BT + t8 + 8);  nB1 = *(const float4*)(BT + t8 + 12);
            nC0 = *(const float4*)(CT + t8 + 8);  nC1 = *(const float4*)(CT + t8 + 12);
        }

        // serial h-chain (true dependency is just the fma), collect p[j]
        float p[8];
#pragma unroll
        for (int j = 0; j < 8; j++) {
            float delta = dv[j];
            float dA = __expf(delta * a);
            h = fmaf(dA, h, (delta * xv[j]) * Bn[j]);
            p[j] = h * Cn[j];
        }

        // 8 independent shfl trees, interleaved (chain depth 4)
#pragma unroll
        for (int off = 8; off >= 1; off >>= 1) {
#pragma unroll
            for (int j = 0; j < 8; j++)
                p[j] += __shfl_xor_sync(0xffffffffu, p[j], off);
        }

        // gate (z pre-silu'd) + D-skip + store
        if (n == 0) {
#pragma unroll
            for (int j = 0; j < 8; j++)
                yp[(size_t)(t8 + j) * DI] = fmaf(xv[j], Dv, p[j]) * zv[j];
        }
    }
}

// ---------------- layernorm over DM=512 ----------------
__global__ __launch_bounds__(256) void ln_k(
    const float* __restrict__ g, const float* __restrict__ bb,
    float* __restrict__ out)
{
    __shared__ float red[256];
    int row = blockIdx.x;
    const float* r = g_res + (size_t)row * DM;
    int tid = threadIdx.x;
    float v0 = r[tid], v1 = r[tid + 256];
    red[tid] = v0 + v1;
    __syncthreads();
    for (int o = 128; o > 0; o >>= 1) {
        if (tid < o) red[tid] += red[tid + o];
        __syncthreads();
    }
    float mean = red[0] * (1.f / 512.f);
    __syncthreads();
    float d0 = v0 - mean, d1 = v1 - mean;
    red[tid] = d0 * d0 + d1 * d1;
    __syncthreads();
    for (int o = 128; o > 0; o >>= 1) {
        if (tid < o) red[tid] += red[tid + o];
        __syncthreads();
    }
    float rs = rsqrtf(red[0] * (1.f / 512.f) + LN_EPS);
    out[(size_t)row * DM + tid]       = d0 * rs * g[tid]       + bb[tid];
    out[(size_t)row * DM + tid + 256] = d1 * rs * g[tid + 256] + bb[tid + 256];
}

// ---------------- host orchestration ----------------
extern "C" void kernel_launch(void* const* d_in, const int* in_sizes, int n_in,
                              void* d_out, int out_size)
{
    const float* x     = (const float*)d_in[0];
    const float* Wi    = (const float*)d_in[1];
    const float* cw    = (const float*)d_in[2];
    const float* cb    = (const float*)d_in[3];
    const float* Wx    = (const float*)d_in[4];
    const float* Wdt   = (const float*)d_in[5];
    const float* bdt   = (const float*)d_in[6];
    const float* A_log = (const float*)d_in[7];
    const float* Dsk   = (const float*)d_in[8];
    const float* Wo    = (const float*)d_in[9];
    const float* lng   = (const float*)d_in[10];
    const float* lnb   = (const float*)d_in[11];
    float* out = (float*)d_out;

    float *p_y, *p_res;
    cudaGetSymbolAddress((void**)&p_y,   g_y);
    cudaGetSymbolAddress((void**)&p_res, g_res);

    for (int l = 0; l < 2; l++) {
        const float* hin = (l == 0) ? x : out;

        // 1) GEMM1: xz = hin @ Wi[l], split-transposed -> g_xinT, silu -> g_zT
        mma_gemm<<<dim3(2 * DI / BN, NROWS / BM), 256>>>(
            hin, Wi + (size_t)l * DM * 2 * DI, nullptr, nullptr,
            DM, DM, 2 * DI, 0, 3);

        // 2) conv + silu: xinT -> xsT (channel-major) + xs (row-major)
        conv2_k<<<dim3(LSEQ / 64, DI / 32, BATCH), 256>>>(
            cw + (size_t)l * DI * 4, cb + (size_t)l * DI);

        // 3) fused x_proj + dt_proj: -> g_BT, g_CT, g_dT
        proj_k<<<NROWS / BM, 256>>>(
            Wx + (size_t)l * DI * 64, Wdt + (size_t)l * DTR * DI,
            bdt + (size_t)l * DI);

        // 4) selective scan (+D skip, +gate fused) -> g_y   [profiled slot]
        scan_k<<<(BATCH * (DI / 2) * 32) / 128, 128>>>(
            A_log + (size_t)l * DI * DS, Dsk + (size_t)l * DI);

        // 5) GEMM4: res = y @ Wo[l] + hin
        mma_gemm<<<dim3(DM / BN, NROWS / BM), 256>>>(
            p_y, Wo + (size_t)l * DI * DM, p_res, hin,
            DI, DI, DM, DM, 1);

        // 6) layernorm -> out
        ln_k<<<NROWS, 256>>>(lng + (size_t)l * DM, lnb + (size_t)l * DM, out);
    }
}

// round 6
// speedup vs baseline: 1.4091x; 1.4091x over previous
#include <cuda_runtime.h>
#include <math.h>
#include <stdint.h>

// ---------------- problem constants ----------------
#define BATCH   4
#define LSEQ    1024
#define DM      512
#define DI      1024      // d_inner
#define DS      16        // d_state
#define DTR     32        // dt_rank
#define NROWS   (BATCH*LSEQ)   // 4096
#define LN_EPS  1e-5f

// ---------------- scratch (device globals; no allocs allowed) ----------------
__device__ float g_xinT[BATCH * DI * LSEQ];   // in_proj x-half, [b][d][t]
__device__ float g_zT  [BATCH * DI * LSEQ];   // silu(z), [b][d][t]
__device__ float g_xsT [BATCH * DI * LSEQ];   // conv+silu, [b][d][t] (scan)
__device__ float g_xs  [NROWS * DI];          // conv+silu, [row][d]  (GEMM2)
__device__ float g_dbc [NROWS * 64];          // x_proj out [row][64] (dt|B|C)
__device__ float g_dT  [BATCH * DI * LSEQ];   // delta, [b][d][t]
__device__ float g_yT  [BATCH * DI * LSEQ];   // scan out (gated), [b][d][t]
__device__ float g_res [NROWS * DM];          // out_proj + residual (LN input)

// ---------------- tf32 helpers ----------------
__device__ __forceinline__ uint32_t f2tf32(float x) {
    uint32_t r;
    asm("cvt.rna.tf32.f32 %0, %1;" : "=r"(r) : "f"(x));
    return r;
}

__device__ __forceinline__ void mma_tf32(
    float& d0, float& d1, float& d2, float& d3,
    uint32_t a0, uint32_t a1, uint32_t a2, uint32_t a3,
    uint32_t b0, uint32_t b1)
{
    asm volatile(
        "mma.sync.aligned.m16n8k8.row.col.f32.tf32.tf32.f32 "
        "{%0,%1,%2,%3}, {%4,%5,%6,%7}, {%8,%9}, {%0,%1,%2,%3};\n"
        : "+f"(d0), "+f"(d1), "+f"(d2), "+f"(d3)
        : "r"(a0), "r"(a1), "r"(a2), "r"(a3), "r"(b0), "r"(b1));
}

__device__ __forceinline__ float silu_f(float x) {
    return __fdividef(x, 1.f + __expf(-x));
}

// ---------------- tensor-core GEMM: C[M,N] = A[M,K] @ B[K,N] ----------------
// modes:
//  0: C[row][col] = acc                              (plain store)
//  1: C[row][col] = acc + aux[row][col]              (residual)
//  2: transposed: C=[b][col][t] = softplus(acc + aux[col])
//  3: transposed split: col<DI -> xinT[b][col][t], else silu -> zT[b][col-DI][t]
// amode: 0 = A row-major [M][lda];  1 = A channel-major [b][d][t] (K=DI)
#define BM 128
#define BN 64
#define BK 32

__global__ __launch_bounds__(256) void mma_gemm(
    const float* __restrict__ A, const float* __restrict__ B,
    float* __restrict__ C, const float* __restrict__ aux,
    int K, int lda, int ldb, int ldc, int mode, int amode)
{
    __shared__ uint32_t As[BM][36];
    __shared__ uint32_t Bs[BK][68];

    const int tid = threadIdx.x;
    const int bm = blockIdx.y * BM;
    const int bn = blockIdx.x * BN;
    const int w  = tid >> 5;
    const int lane = tid & 31;
    const int g  = lane >> 2;
    const int tg = lane & 3;
    const int wm = (w & 3) * 32;
    const int wn = (w >> 2) * 32;

    const int ra = tid >> 3;
    const int ca = (tid & 7) * 4;
    const int rb = tid >> 4;
    const int cb = (tid & 15) * 4;

    // amode 1 coords
    const int bA = bm >> 10;
    const int tbase = bm & (LSEQ - 1);
    const int dA = tid >> 3;           // 0..31 (k within BK)
    const int tA = (tid & 7) * 4;      // t within 32-chunk

    float acc[2][4][4];
#pragma unroll
    for (int i = 0; i < 2; i++)
#pragma unroll
        for (int j = 0; j < 4; j++)
#pragma unroll
            for (int r = 0; r < 4; r++) acc[i][j][r] = 0.f;

    const int nk = K / BK;

    float4 pa[4], pb[2];
    if (amode == 0) {
#pragma unroll
        for (int p = 0; p < 4; p++)
            pa[p] = *(const float4*)(A + (size_t)(bm + ra + p * 32) * lda + ca);
    } else {
#pragma unroll
        for (int p = 0; p < 4; p++)
            pa[p] = *(const float4*)(A + ((size_t)(bA * DI + dA)) * LSEQ
                                     + tbase + p * 32 + tA);
    }
#pragma unroll
    for (int p = 0; p < 2; p++)
        pb[p] = *(const float4*)(B + (size_t)(rb + p * 16) * ldb + bn + cb);

    for (int kb = 0; kb < nk; kb++) {
        if (amode == 0) {
#pragma unroll
            for (int p = 0; p < 4; p++) {
                uint4 v;
                v.x = f2tf32(pa[p].x); v.y = f2tf32(pa[p].y);
                v.z = f2tf32(pa[p].z); v.w = f2tf32(pa[p].w);
                *(uint4*)&As[ra + p * 32][ca] = v;
            }
        } else {
            // transpose commit: As[t][d]
#pragma unroll
            for (int p = 0; p < 4; p++) {
                As[p * 32 + tA + 0][dA] = f2tf32(pa[p].x);
                As[p * 32 + tA + 1][dA] = f2tf32(pa[p].y);
                As[p * 32 + tA + 2][dA] = f2tf32(pa[p].z);
                As[p * 32 + tA + 3][dA] = f2tf32(pa[p].w);
            }
        }
#pragma unroll
        for (int p = 0; p < 2; p++) {
            uint4 v;
            v.x = f2tf32(pb[p].x); v.y = f2tf32(pb[p].y);
            v.z = f2tf32(pb[p].z); v.w = f2tf32(pb[p].w);
            *(uint4*)&Bs[rb + p * 16][cb] = v;
        }
        __syncthreads();

        if (kb + 1 < nk) {
            int k0 = (kb + 1) * BK;
            if (amode == 0) {
#pragma unroll
                for (int p = 0; p < 4; p++)
                    pa[p] = *(const float4*)(A + (size_t)(bm + ra + p * 32) * lda + k0 + ca);
            } else {
#pragma unroll
                for (int p = 0; p < 4; p++)
                    pa[p] = *(const float4*)(A + ((size_t)(bA * DI + k0 + dA)) * LSEQ
                                             + tbase + p * 32 + tA);
            }
#pragma unroll
            for (int p = 0; p < 2; p++)
                pb[p] = *(const float4*)(B + (size_t)(k0 + rb + p * 16) * ldb + bn + cb);
        }

#pragma unroll
        for (int ks = 0; ks < 4; ks++) {
            const int k8 = ks * 8;
            uint32_t af[2][4];
#pragma unroll
            for (int mt = 0; mt < 2; mt++) {
                int r0 = wm + mt * 16 + g;
                af[mt][0] = As[r0][k8 + tg];
                af[mt][1] = As[r0 + 8][k8 + tg];
                af[mt][2] = As[r0][k8 + tg + 4];
                af[mt][3] = As[r0 + 8][k8 + tg + 4];
            }
#pragma unroll
            for (int nt = 0; nt < 4; nt++) {
                int c0 = wn + nt * 8 + g;
                uint32_t b0 = Bs[k8 + tg][c0];
                uint32_t b1 = Bs[k8 + tg + 4][c0];
#pragma unroll
                for (int mt = 0; mt < 2; mt++)
                    mma_tf32(acc[mt][nt][0], acc[mt][nt][1],
                             acc[mt][nt][2], acc[mt][nt][3],
                             af[mt][0], af[mt][1], af[mt][2], af[mt][3],
                             b0, b1);
            }
        }
        __syncthreads();
    }

#pragma unroll
    for (int mt = 0; mt < 2; mt++) {
#pragma unroll
        for (int nt = 0; nt < 4; nt++) {
            int grow = bm + wm + mt * 16 + g;
            int gcol = bn + wn + nt * 8 + 2 * tg;
            float v0 = acc[mt][nt][0], v1 = acc[mt][nt][1];
            float v2 = acc[mt][nt][2], v3 = acc[mt][nt][3];
            if (mode <= 1) {
                if (mode == 1) {
                    float2 r0 = *(const float2*)(aux + (size_t)grow * ldc + gcol);
                    float2 r1 = *(const float2*)(aux + (size_t)(grow + 8) * ldc + gcol);
                    v0 += r0.x; v1 += r0.y; v2 += r1.x; v3 += r1.y;
                }
                float2 o0 = {v0, v1}, o1 = {v2, v3};
                *(float2*)(C + (size_t)grow * ldc + gcol) = o0;
                *(float2*)(C + (size_t)(grow + 8) * ldc + gcol) = o1;
            } else {
                int b = grow >> 10;
                int t = grow & (LSEQ - 1);
                if (mode == 2) {
                    float b0 = aux[gcol], b1 = aux[gcol + 1];
                    v0 += b0; v1 += b1; v2 += b0; v3 += b1;
                    v0 = (v0 > 20.f) ? v0 : __logf(1.f + __expf(v0));
                    v1 = (v1 > 20.f) ? v1 : __logf(1.f + __expf(v1));
                    v2 = (v2 > 20.f) ? v2 : __logf(1.f + __expf(v2));
                    v3 = (v3 > 20.f) ? v3 : __logf(1.f + __expf(v3));
                    float* base = C + ((size_t)b * DI) * LSEQ;
                    base[(size_t)gcol * LSEQ + t]           = v0;
                    base[(size_t)(gcol + 1) * LSEQ + t]     = v1;
                    base[(size_t)gcol * LSEQ + t + 8]       = v2;
                    base[(size_t)(gcol + 1) * LSEQ + t + 8] = v3;
                } else { // mode 3: split-transpose (xin | silu(z))
                    float* dst;
                    int c;
                    if (gcol < DI) { dst = g_xinT; c = gcol; }
                    else {
                        dst = g_zT; c = gcol - DI;
                        v0 = silu_f(v0); v1 = silu_f(v1);
                        v2 = silu_f(v2); v3 = silu_f(v3);
                    }
                    float* base = dst + ((size_t)b * DI) * LSEQ;
                    base[(size_t)c * LSEQ + t]           = v0;
                    base[(size_t)(c + 1) * LSEQ + t]     = v1;
                    base[(size_t)c * LSEQ + t + 8]       = v2;
                    base[(size_t)(c + 1) * LSEQ + t + 8] = v3;
                }
            }
        }
    }
}

// ---------------- depthwise causal conv (k=4) + bias + silu, channel-major --
__global__ __launch_bounds__(256) void conv2_k(
    const float* __restrict__ cw, const float* __restrict__ cb)
{
    __shared__ float tin[32][68];
    __shared__ float tout[32][65];
    const int b  = blockIdx.z;
    const int d0 = blockIdx.y * 32;
    const int t0 = blockIdx.x * 64;
    const int tid = threadIdx.x;

    for (int i = tid; i < 32 * 67; i += 256) {
        int dd = i / 67, j = i % 67;
        int t = t0 - 3 + j;
        float v = 0.f;
        if (t >= 0) v = g_xinT[((size_t)(b * DI + d0 + dd)) * LSEQ + t];
        tin[dd][j] = v;
    }
    __syncthreads();

    const int dd = tid >> 3;
    const int tq = tid & 7;
    const float* wp = cw + (d0 + dd) * 4;
    float w0 = wp[0], w1 = wp[1], w2 = wp[2], w3 = wp[3];
    float bias = cb[d0 + dd];

    float res[8];
#pragma unroll
    for (int half = 0; half < 2; half++) {
#pragma unroll
        for (int i = 0; i < 4; i++) {
            int j = half * 32 + tq * 4 + i;
            float acc = bias;
            acc = fmaf(w0, tin[dd][j],     acc);
            acc = fmaf(w1, tin[dd][j + 1], acc);
            acc = fmaf(w2, tin[dd][j + 2], acc);
            acc = fmaf(w3, tin[dd][j + 3], acc);
            acc = silu_f(acc);
            res[half * 4 + i] = acc;
            tout[dd][j] = acc;
        }
    }
    float* dstT = g_xsT + ((size_t)(b * DI + d0 + dd)) * LSEQ + t0;
    *(float4*)(dstT + tq * 4)      = make_float4(res[0], res[1], res[2], res[3]);
    *(float4*)(dstT + 32 + tq * 4) = make_float4(res[4], res[5], res[6], res[7]);
    __syncthreads();

    const int dw = tid & 31;
    const int tw = tid >> 5;
#pragma unroll
    for (int it = 0; it < 8; it++) {
        int tl = it * 8 + tw;
        g_xs[((size_t)(b * LSEQ + t0 + tl)) * DI + d0 + dw] = tout[dw][tl];
    }
}

// ---------------- selective scan, low-wavefront streams -----------------
// 16 lanes per channel (one state each), 2 channels per warp.
// d/x/z streams: contiguous float4, broadcast within half-warp.
// B/C: row-major dbc reads -> 64B broadcast segments.
// y: channel-major float4 stores.
__global__ __launch_bounds__(128) void scan_k(
    const float* __restrict__ A_log, const float* __restrict__ Dsk)
{
    int tid = blockIdx.x * 128 + threadIdx.x;
    int w = tid >> 5;
    int lane = tid & 31;
    int half = lane >> 4;
    int n = lane & 15;
    int b = w / (DI / 2);
    int dp = w % (DI / 2);
    int d = dp * 2 + half;

    const float a  = -expf(A_log[d * DS + n]);
    const float Dv = Dsk[d];

    const float* dT = g_dT  + ((size_t)(b * DI + d)) * LSEQ;
    const float* xT = g_xsT + ((size_t)(b * DI + d)) * LSEQ;
    const float* zT = g_zT  + ((size_t)(b * DI + d)) * LSEQ;
    const float* bc = g_dbc + ((size_t)b * LSEQ) * 64;
    float*       yT = g_yT  + ((size_t)(b * DI + d)) * LSEQ;

    // prefetch one 8-step group ahead
    float4 nd0 = *(const float4*)(dT),     nd1 = *(const float4*)(dT + 4);
    float4 nx0 = *(const float4*)(xT),     nx1 = *(const float4*)(xT + 4);
    float4 nz0 = *(const float4*)(zT),     nz1 = *(const float4*)(zT + 4);
    float nB[8], nC[8];
#pragma unroll
    for (int j = 0; j < 8; j++) {
        nB[j] = __ldg(bc + (size_t)j * 64 + 32 + n);
        nC[j] = __ldg(bc + (size_t)j * 64 + 48 + n);
    }

    float h = 0.f;
    for (int t8 = 0; t8 < LSEQ; t8 += 8) {
        float dv[8] = {nd0.x, nd0.y, nd0.z, nd0.w, nd1.x, nd1.y, nd1.z, nd1.w};
        float xv[8] = {nx0.x, nx0.y, nx0.z, nx0.w, nx1.x, nx1.y, nx1.z, nx1.w};
        float zv[8] = {nz0.x, nz0.y, nz0.z, nz0.w, nz1.x, nz1.y, nz1.z, nz1.w};
        float Bn[8], Cn[8];
#pragma unroll
        for (int j = 0; j < 8; j++) { Bn[j] = nB[j]; Cn[j] = nC[j]; }

        if (t8 + 8 < LSEQ) {
            nd0 = *(const float4*)(dT + t8 + 8);  nd1 = *(const float4*)(dT + t8 + 12);
            nx0 = *(const float4*)(xT + t8 + 8);  nx1 = *(const float4*)(xT + t8 + 12);
            nz0 = *(const float4*)(zT + t8 + 8);  nz1 = *(const float4*)(zT + t8 + 12);
            const float* bcn = bc + (size_t)(t8 + 8) * 64;
#pragma unroll
            for (int j = 0; j < 8; j++) {
                nB[j] = __ldg(bcn + (size_t)j * 64 + 32 + n);
                nC[j] = __ldg(bcn + (size_t)j * 64 + 48 + n);
            }
        }

        // serial h-chain (true dependency is only the fma), collect p[j]
        float p[8];
#pragma unroll
        for (int j = 0; j < 8; j++) {
            float delta = dv[j];
            float dA = __expf(delta * a);
            h = fmaf(dA, h, (delta * xv[j]) * Bn[j]);
            p[j] = h * Cn[j];
        }

        // 8 independent shfl trees, interleaved (chain depth 4)
#pragma unroll
        for (int off = 8; off >= 1; off >>= 1) {
#pragma unroll
            for (int j = 0; j < 8; j++)
                p[j] += __shfl_xor_sync(0xffffffffu, p[j], off);
        }

        // gate (z pre-silu'd) + D-skip + contiguous store
        if (n == 0) {
            float y0 = fmaf(xv[0], Dv, p[0]) * zv[0];
            float y1 = fmaf(xv[1], Dv, p[1]) * zv[1];
            float y2 = fmaf(xv[2], Dv, p[2]) * zv[2];
            float y3 = fmaf(xv[3], Dv, p[3]) * zv[3];
            float y4 = fmaf(xv[4], Dv, p[4]) * zv[4];
            float y5 = fmaf(xv[5], Dv, p[5]) * zv[5];
            float y6 = fmaf(xv[6], Dv, p[6]) * zv[6];
            float y7 = fmaf(xv[7], Dv, p[7]) * zv[7];
            *(float4*)(yT + t8)     = make_float4(y0, y1, y2, y3);
            *(float4*)(yT + t8 + 4) = make_float4(y4, y5, y6, y7);
        }
    }
}

// ---------------- layernorm over DM=512 ----------------
__global__ __launch_bounds__(256) void ln_k(
    const float* __restrict__ g, const float* __restrict__ bb,
    float* __restrict__ out)
{
    __shared__ float red[256];
    int row = blockIdx.x;
    const float* r = g_res + (size_t)row * DM;
    int tid = threadIdx.x;
    float v0 = r[tid], v1 = r[tid + 256];
    red[tid] = v0 + v1;
    __syncthreads();
    for (int o = 128; o > 0; o >>= 1) {
        if (tid < o) red[tid] += red[tid + o];
        __syncthreads();
    }
    float mean = red[0] * (1.f / 512.f);
    __syncthreads();
    float d0 = v0 - mean, d1 = v1 - mean;
    red[tid] = d0 * d0 + d1 * d1;
    __syncthreads();
    for (int o = 128; o > 0; o >>= 1) {
        if (tid < o) red[tid] += red[tid + o];
        __syncthreads();
    }
    float rs = rsqrtf(red[0] * (1.f / 512.f) + LN_EPS);
    out[(size_t)row * DM + tid]       = d0 * rs * g[tid]       + bb[tid];
    out[(size_t)row * DM + tid + 256] = d1 * rs * g[tid + 256] + bb[tid + 256];
}

// ---------------- host orchestration ----------------
extern "C" void kernel_launch(void* const* d_in, const int* in_sizes, int n_in,
                              void* d_out, int out_size)
{
    const float* x     = (const float*)d_in[0];
    const float* Wi    = (const float*)d_in[1];
    const float* cw    = (const float*)d_in[2];
    const float* cb    = (const float*)d_in[3];
    const float* Wx    = (const float*)d_in[4];
    const float* Wdt   = (const float*)d_in[5];
    const float* bdt   = (const float*)d_in[6];
    const float* A_log = (const float*)d_in[7];
    const float* Dsk   = (const float*)d_in[8];
    const float* Wo    = (const float*)d_in[9];
    const float* lng   = (const float*)d_in[10];
    const float* lnb   = (const float*)d_in[11];
    float* out = (float*)d_out;

    float *p_xs, *p_dbc, *p_dT, *p_yT, *p_res;
    cudaGetSymbolAddress((void**)&p_xs,  g_xs);
    cudaGetSymbolAddress((void**)&p_dbc, g_dbc);
    cudaGetSymbolAddress((void**)&p_dT,  g_dT);
    cudaGetSymbolAddress((void**)&p_yT,  g_yT);
    cudaGetSymbolAddress((void**)&p_res, g_res);

    for (int l = 0; l < 2; l++) {
        const float* hin = (l == 0) ? x : out;

        // 1) GEMM1: xz = hin @ Wi[l], split-transposed -> g_xinT, silu -> g_zT
        mma_gemm<<<dim3(2 * DI / BN, NROWS / BM), 256>>>(
            hin, Wi + (size_t)l * DM * 2 * DI, nullptr, nullptr,
            DM, DM, 2 * DI, 0, 3, 0);

        // 2) conv + silu: xinT -> xsT (channel-major) + xs (row-major)
        conv2_k<<<dim3(LSEQ / 64, DI / 32, BATCH), 256>>>(
            cw + (size_t)l * DI * 4, cb + (size_t)l * DI);

        // 3) GEMM2: dbc = xs @ Wx[l]  [4096,1024]x[1024,64], row-major
        mma_gemm<<<dim3(1, NROWS / BM), 256>>>(
            p_xs, Wx + (size_t)l * DI * 64, p_dbc, nullptr,
            DI, DI, 64, 64, 0, 0);

        // 4) GEMM3: deltaT = softplus(dt @ Wdt[l] + bdt), transposed out
        mma_gemm<<<dim3(DI / BN, NROWS / BM), 256>>>(
            p_dbc, Wdt + (size_t)l * DTR * DI, p_dT, bdt + (size_t)l * DI,
            DTR, 64, DI, 0, 2, 0);

        // 5) selective scan (+D skip, +gate fused) -> g_yT channel-major
        scan_k<<<(BATCH * (DI / 2) * 32) / 128, 128>>>(
            A_log + (size_t)l * DI * DS, Dsk + (size_t)l * DI);

        // 6) GEMM4: res = yT @ Wo[l] + hin (A channel-major)
        mma_gemm<<<dim3(DM / BN, NROWS / BM), 256>>>(
            p_yT, Wo + (size_t)l * DI * DM, p_res, hin,
            DI, 0, DM, DM, 1, 1);

        // 7) layernorm -> out
        ln_k<<<NROWS, 256>>>(lng + (size_t)l * DM, lnb + (size_t)l * DM, out);
    }
}